// round 9
// baseline (speedup 1.0000x reference)
#include <cuda_runtime.h>
#include <cuda_bf16.h>

// firing_model: next = -prev + tanh(prev @ x) from prev = 0 -> identically
// zero trajectory (tanh(0) = 0 exactly in fp32; time_fomer never influences
// the returned rows). Output [499800, 69] is all zeros -> pure 138 MB
// zero-fill of d_out.
//
// CONVERGED (final, validated R3/R7/R8): kernel pinned at ~20 us =
// 137.9 MB at ~6.9 TB/s HBM3e write stream (effective ceiling; LTS cap is
// path-independent so TMA/other store paths offer no headroom). Total adds
// ~2.8 us fixed graph-replay overhead. Run-to-run noise on identical code:
// 22.62-23.01 us. Geometry: exact-cover, 2 contiguous streaming STG.128
// per thread, 16 KB per block.

#define FILL_THREADS 256
#define F4_PER_THREAD 2   // each block covers FILL_THREADS * 2 float4s

__global__ void __launch_bounds__(FILL_THREADS)
firing_model_zero_fill2(float4* __restrict__ out, long long n4) {
    long long base = (long long)blockIdx.x * (FILL_THREADS * F4_PER_THREAD)
                   + threadIdx.x;
    const float4 z = make_float4(0.0f, 0.0f, 0.0f, 0.0f);

    long long i0 = base;
    long long i1 = base + FILL_THREADS;
    if (i0 < n4) __stcs(&out[i0], z);
    if (i1 < n4) __stcs(&out[i1], z);
}

__global__ void firing_model_zero_fill_tail(float* __restrict__ out,
                                            long long start, long long n) {
    long long i = start + (long long)blockIdx.x * blockDim.x + threadIdx.x;
    if (i < n) {
        out[i] = 0.0f;
    }
}

extern "C" void kernel_launch(void* const* d_in, const int* in_sizes, int n_in,
                              void* d_out, int out_size) {
    (void)d_in; (void)in_sizes; (void)n_in;

    float* out = (float*)d_out;
    long long n  = (long long)out_size;   // 34,486,200 floats expected
    long long n4 = n >> 2;                // 8,621,550 float4s (exact for this shape)
    long long tail_start = n4 << 2;

    if (n4 > 0) {
        long long per_block = FILL_THREADS * F4_PER_THREAD;
        long long blocks = (n4 + per_block - 1) / per_block;   // ~16,839
        firing_model_zero_fill2<<<(unsigned int)blocks, FILL_THREADS>>>(
            (float4*)out, n4);
    }
    if (tail_start < n) {  // not taken for this shape; defensive
        long long tail = n - tail_start;
        int blocks = (int)((tail + 255) / 256);
        firing_model_zero_fill_tail<<<blocks, 256>>>(out, tail_start, n);
    }
}

// round 10
// speedup vs baseline: 1.0097x; 1.0097x over previous
#include <cuda_runtime.h>
#include <cuda_bf16.h>

// firing_model: next = -prev + tanh(prev @ x) from prev = 0 -> identically
// zero trajectory (tanh(0) = 0 exactly in fp32; time_fomer never influences
// the returned rows). Output [499800, 69] is all zeros -> pure 138 MB
// zero-fill of d_out.
//
// CONVERGED (validated over R3/R7/R8/R9, identical binary): kernel
// 19.8-20.3 us = 137.9 MB at ~6.9 TB/s HBM3e write stream (effective
// ceiling; LTS cap is path-independent so no store path has headroom).
// Total = kernel + ~2.8 us fixed graph-replay overhead; run-to-run noise
// band 22.6-23.3 us. Geometry: exact-cover, 2 contiguous streaming STG.128
// per thread, 16 KB per block. R10: 32-bit indexing (n4 = 8,621,550 fits
// int) — cosmetic prologue trim, zero regression risk.

#define FILL_THREADS 256
#define F4_PER_THREAD 2   // each block covers FILL_THREADS * 2 float4s

__global__ void __launch_bounds__(FILL_THREADS)
firing_model_zero_fill2(float4* __restrict__ out, int n4) {
    int base = blockIdx.x * (FILL_THREADS * F4_PER_THREAD) + threadIdx.x;
    const float4 z = make_float4(0.0f, 0.0f, 0.0f, 0.0f);

    int i0 = base;
    int i1 = base + FILL_THREADS;
    if (i0 < n4) __stcs(&out[i0], z);
    if (i1 < n4) __stcs(&out[i1], z);
}

__global__ void firing_model_zero_fill_tail(float* __restrict__ out,
                                            long long start, long long n) {
    long long i = start + (long long)blockIdx.x * blockDim.x + threadIdx.x;
    if (i < n) {
        out[i] = 0.0f;
    }
}

extern "C" void kernel_launch(void* const* d_in, const int* in_sizes, int n_in,
                              void* d_out, int out_size) {
    (void)d_in; (void)in_sizes; (void)n_in;

    float* out = (float*)d_out;
    long long n  = (long long)out_size;   // 34,486,200 floats expected
    long long n4 = n >> 2;                // 8,621,550 float4s (exact for this shape)
    long long tail_start = n4 << 2;

    if (n4 > 0) {
        long long per_block = FILL_THREADS * F4_PER_THREAD;
        long long blocks = (n4 + per_block - 1) / per_block;   // ~16,839
        firing_model_zero_fill2<<<(unsigned int)blocks, FILL_THREADS>>>(
            (float4*)out, (int)n4);
    }
    if (tail_start < n) {  // not taken for this shape; defensive
        long long tail = n - tail_start;
        int blocks = (int)((tail + 255) / 256);
        firing_model_zero_fill_tail<<<blocks, 256>>>(out, tail_start, n);
    }
}